// round 1
// baseline (speedup 1.0000x reference)
#include <cuda_runtime.h>
#include <cuda_bf16.h>
#include <mma.h>

using namespace nvcuda;

// Problem constants
#define BATCH 128
#define TVIEW 196      // T
#define TTOT  392      // 2T
#define ENC   1024
#define DEC   512
#define NVIS  98       // V
#define NMASK 294      // M

// Scratch: rank per (b, token) [-1 if masked], and token per (b, visible-rank)
__device__ int g_rank[BATCH * TTOT];
__device__ int g_vis_tok[BATCH * NVIS];

// ---------------------------------------------------------------------------
// Kernel A: build visible-id index per batch row.
// One block per batch row. Detects int32 vs int64 masked_ids at runtime.
// ---------------------------------------------------------------------------
__global__ void build_index_kernel(const void* __restrict__ mids_raw) {
    __shared__ int flags[TTOT];
    __shared__ int scanv[512];
    __shared__ int is64;

    const int b = blockIdx.x;
    const int t = threadIdx.x;

    if (t == 0) {
        // If the buffer is int64 (little-endian), every odd 32-bit word of the
        // first 64 entries is 0 and every even word < 392. If it's int32, the
        // odd words are random ids in [0,392) -> virtually impossible to all be 0.
        const unsigned int* w = (const unsigned int*)mids_raw;
        int ok = 1;
        #pragma unroll 1
        for (int i = 0; i < 64; i++) {
            if (w[2 * i + 1] != 0u || w[2 * i] >= (unsigned)TTOT) { ok = 0; break; }
        }
        is64 = ok;
    }
    if (t < TTOT) flags[t] = 1;
    __syncthreads();

    if (is64) {
        const long long* m64 = (const long long*)mids_raw;
        for (int i = t; i < NMASK; i += blockDim.x)
            flags[(int)m64[(size_t)b * NMASK + i]] = 0;
    } else {
        const int* m32 = (const int*)mids_raw;
        for (int i = t; i < NMASK; i += blockDim.x)
            flags[m32[b * NMASK + i]] = 0;
    }
    __syncthreads();

    const int f = (t < TTOT) ? flags[t] : 0;
    scanv[t] = f;
    // Hillis-Steele inclusive scan over 512 slots
    for (int off = 1; off < 512; off <<= 1) {
        __syncthreads();
        int v = scanv[t];
        int u = (t >= off) ? scanv[t - off] : 0;
        __syncthreads();
        scanv[t] = v + u;
    }
    __syncthreads();

    if (t < TTOT) {
        if (f) {
            int r = scanv[t] - 1;
            g_rank[b * TTOT + t] = r;
            g_vis_tok[b * NVIS + r] = t;
        } else {
            g_rank[b * TTOT + t] = -1;
        }
    }
}

// ---------------------------------------------------------------------------
// Kernel C: fill masked rows with mask_token + pos_embed + view_embed.
// One warp per (b, token) row; skip visible rows.
// ---------------------------------------------------------------------------
__global__ void fill_masked_kernel(const float* __restrict__ mask_token,
                                   const float* __restrict__ pos,
                                   const float* __restrict__ ve,
                                   float* __restrict__ out) {
    const int warp = (blockIdx.x * blockDim.x + threadIdx.x) >> 5;
    const int lane = threadIdx.x & 31;
    if (warp >= BATCH * TTOT) return;
    if (g_rank[warp] >= 0) return;  // visible -> written by GEMM epilogue

    const int t = warp % TTOT;
    const float4* mt = (const float4*)mask_token;
    const float4* pp = (const float4*)(pos + (size_t)t * DEC);
    const float4* vv = (const float4*)(ve + (size_t)(t >= TVIEW) * DEC);
    float4* o = (float4*)(out + (size_t)warp * DEC);

    #pragma unroll
    for (int j = 0; j < 4; j++) {
        int i = lane + j * 32;            // 128 float4 per row
        float4 a = mt[i], p = pp[i], c = vv[i];
        o[i] = make_float4(a.x + p.x + c.x, a.y + p.y + c.y,
                           a.z + p.z + c.z, a.w + p.w + c.w);
    }
}

// ---------------------------------------------------------------------------
// Kernel B: TF32 wmma GEMM (M=12544, N=512, K=1024), epilogue scatters each
// output row to out[b, visible_tok, :] adding bias + pos_embed + view_embed.
// Block tile 128x64, 8 warps (4x2), each warp 32x32 via 2x2 wmma 16x16x8 frags.
// ---------------------------------------------------------------------------
#define BM 128
#define BN 64
#define BK 16
#define LDA (BK + 4)   // 20
#define LDB (BN + 4)   // 68
#define LDC (BN + 4)   // 68

__global__ void gemm_scatter_kernel(const float* __restrict__ x,
                                    const float* __restrict__ W,
                                    const float* __restrict__ bias,
                                    const float* __restrict__ pos,
                                    const float* __restrict__ ve,
                                    float* __restrict__ out) {
    extern __shared__ float smem[];
    float* As = smem;                  // [BM][LDA]  = 2560 floats
    float* Bs = smem + BM * LDA;       // [BK][LDB]  = 1088 floats
    float* Cs = smem;                  // reused after mainloop: [BM][LDC]

    const int bm = blockIdx.x;         // 0..97
    const int bn = blockIdx.y;         // 0..7
    const int tid = threadIdx.x;       // 256 threads
    const int wid = tid >> 5;
    const int lane = tid & 31;
    const int wr = wid >> 1;           // warp row 0..3  -> rows wr*32..+31
    const int wc = wid & 1;            // warp col 0..1  -> cols wc*32..+31

    wmma::fragment<wmma::accumulator, 16, 16, 8, float> acc[2][2];
    #pragma unroll
    for (int i = 0; i < 2; i++)
        #pragma unroll
        for (int j = 0; j < 2; j++)
            wmma::fill_fragment(acc[i][j], 0.0f);

    const int row0 = bm * BM;
    const int ar = tid >> 1;           // 0..127 row in A tile
    const int aseg = tid & 1;          // 8-col segment
    const int bn_local = tid & 63;     // 0..63 n within B tile
    const int bkq = tid >> 6;          // 0..3 -> k offset bkq*4

    for (int k0 = 0; k0 < ENC; k0 += BK) {
        // A tile: 128 rows x 16 k (2 float4 per thread)
        {
            const float4* src = (const float4*)(x + (size_t)(row0 + ar) * ENC + k0 + aseg * 8);
            float4 v0 = src[0], v1 = src[1];
            float* dst = As + ar * LDA + aseg * 8;
            *(float4*)(dst) = v0;
            *(float4*)(dst + 4) = v1;
        }
        // B tile: W is (DEC, ENC) row-major; we need Bs[k][n] = W[n_glob][k_glob]
        {
            const float4 v = *(const float4*)(W + (size_t)(bn * BN + bn_local) * ENC + k0 + bkq * 4);
            Bs[(bkq * 4 + 0) * LDB + bn_local] = v.x;
            Bs[(bkq * 4 + 1) * LDB + bn_local] = v.y;
            Bs[(bkq * 4 + 2) * LDB + bn_local] = v.z;
            Bs[(bkq * 4 + 3) * LDB + bn_local] = v.w;
        }
        __syncthreads();

        #pragma unroll
        for (int kk = 0; kk < BK; kk += 8) {
            wmma::fragment<wmma::matrix_a, 16, 16, 8, wmma::precision::tf32, wmma::row_major> af[2];
            wmma::fragment<wmma::matrix_b, 16, 16, 8, wmma::precision::tf32, wmma::row_major> bf[2];
            #pragma unroll
            for (int i = 0; i < 2; i++) {
                wmma::load_matrix_sync(af[i], As + (wr * 32 + i * 16) * LDA + kk, LDA);
                #pragma unroll
                for (int e = 0; e < af[i].num_elements; e++)
                    af[i].x[e] = wmma::__float_to_tf32(af[i].x[e]);
            }
            #pragma unroll
            for (int j = 0; j < 2; j++) {
                wmma::load_matrix_sync(bf[j], Bs + kk * LDB + wc * 32 + j * 16, LDB);
                #pragma unroll
                for (int e = 0; e < bf[j].num_elements; e++)
                    bf[j].x[e] = wmma::__float_to_tf32(bf[j].x[e]);
            }
            #pragma unroll
            for (int i = 0; i < 2; i++)
                #pragma unroll
                for (int j = 0; j < 2; j++)
                    wmma::mma_sync(acc[i][j], af[i], bf[j], acc[i][j]);
        }
        __syncthreads();
    }

    // Stage block tile to shared, then scatter rows to global with fused adds.
    #pragma unroll
    for (int i = 0; i < 2; i++)
        #pragma unroll
        for (int j = 0; j < 2; j++)
            wmma::store_matrix_sync(Cs + (wr * 32 + i * 16) * LDC + wc * 32 + j * 16,
                                    acc[i][j], LDC, wmma::mem_row_major);
    __syncthreads();

    // Each warp writes 16 rows; lanes cover 64 cols as float2.
    const int ncol0 = bn * BN + lane * 2;
    #pragma unroll 1
    for (int rr = 0; rr < 16; rr++) {
        const int r = wid * 16 + rr;
        const int m = row0 + r;                 // m = b*98 + v
        const int b = m / NVIS;
        const int tok = g_vis_tok[m];
        const int viewi = (tok >= TVIEW);
        float2 c = *(float2*)(Cs + r * LDC + lane * 2);
        float2 o;
        o.x = c.x + bias[ncol0]     + pos[tok * DEC + ncol0]     + ve[viewi * DEC + ncol0];
        o.y = c.y + bias[ncol0 + 1] + pos[tok * DEC + ncol0 + 1] + ve[viewi * DEC + ncol0 + 1];
        *(float2*)(out + ((size_t)(b * TTOT + tok)) * DEC + ncol0) = o;
    }
}

// ---------------------------------------------------------------------------
extern "C" void kernel_launch(void* const* d_in, const int* in_sizes, int n_in,
                              void* d_out, int out_size) {
    const float* x          = (const float*)d_in[0];
    const void*  mids       = d_in[1];
    const float* W          = (const float*)d_in[2];
    const float* bias       = (const float*)d_in[3];
    const float* mask_token = (const float*)d_in[4];
    const float* pos        = (const float*)d_in[5];
    const float* ve         = (const float*)d_in[6];
    float* out = (float*)d_out;

    // 1) build visibility index
    build_index_kernel<<<BATCH, 512>>>(mids);

    // 2) fill masked rows (one warp per row, B*2T rows)
    {
        const int nwarps = BATCH * TTOT;
        const int threads = 256;
        const int blocks = (nwarps * 32 + threads - 1) / threads;
        fill_masked_kernel<<<blocks, threads>>>(mask_token, pos, ve, out);
    }

    // 3) GEMM + scatter epilogue
    {
        dim3 grid(98, 8);  // M/128, N/64
        size_t smem_bytes = (size_t)BM * LDC * sizeof(float);  // 34816 B (covers A+B too)
        gemm_scatter_kernel<<<grid, 256, smem_bytes>>>(x, W, bias, pos, ve, out);
    }
}

// round 4
// speedup vs baseline: 3.1929x; 3.1929x over previous
#include <cuda_runtime.h>
#include <cuda_fp16.h>
#include <cstdint>

// Problem constants
#define BATCH 128
#define TVIEW 196      // T
#define TTOT  392      // 2T
#define ENC   1024
#define DEC   512
#define NVIS  98       // V
#define NMASK 294      // M

#define MROWS (BATCH * NVIS)   // 12544

// Scratch
__device__ int g_rank[BATCH * TTOT];
__device__ int g_vis_tok[BATCH * NVIS];
__device__ __align__(16) __half g_xh[MROWS * ENC];   // 25.7 MB fp16 copy of x
__device__ __align__(16) __half g_wh[DEC * ENC];     // 1 MB fp16 copy of W

// ---------------------------------------------------------------------------
// helpers
// ---------------------------------------------------------------------------
__device__ __forceinline__ uint32_t smem_u32(const void* p) {
    uint32_t a;
    asm("{ .reg .u64 t; cvta.to.shared.u64 t, %1; cvt.u32.u64 %0, t; }" : "=r"(a) : "l"(p));
    return a;
}
__device__ __forceinline__ void cp_async16(uint32_t dst, const void* src) {
    asm volatile("cp.async.cg.shared.global [%0], [%1], 16;" :: "r"(dst), "l"(src) : "memory");
}
#define CP_COMMIT() asm volatile("cp.async.commit_group;" ::: "memory")
#define CP_WAIT(n)  asm volatile("cp.async.wait_group %0;" :: "n"(n) : "memory")

__device__ __forceinline__ void ldsm4(uint32_t* r, uint32_t addr) {
    asm volatile("ldmatrix.sync.aligned.m8n8.x4.shared.b16 {%0,%1,%2,%3}, [%4];"
                 : "=r"(r[0]), "=r"(r[1]), "=r"(r[2]), "=r"(r[3]) : "r"(addr));
}
__device__ __forceinline__ void mma16816(float* c, const uint32_t* a, const uint32_t* b) {
    asm volatile("mma.sync.aligned.m16n8k16.row.col.f32.f16.f16.f32 "
                 "{%0,%1,%2,%3}, {%4,%5,%6,%7}, {%8,%9}, {%0,%1,%2,%3};"
                 : "+f"(c[0]), "+f"(c[1]), "+f"(c[2]), "+f"(c[3])
                 : "r"(a[0]), "r"(a[1]), "r"(a[2]), "r"(a[3]), "r"(b[0]), "r"(b[1]));
}

// ---------------------------------------------------------------------------
// Kernel A: build visible-id index per batch row (dtype auto-detect).
// ---------------------------------------------------------------------------
__global__ void build_index_kernel(const void* __restrict__ mids_raw) {
    __shared__ int flags[TTOT];
    __shared__ int scanv[512];
    __shared__ int is64;

    const int b = blockIdx.x;
    const int t = threadIdx.x;

    if (t == 0) {
        const unsigned int* w = (const unsigned int*)mids_raw;
        int ok = 1;
        #pragma unroll 1
        for (int i = 0; i < 64; i++) {
            if (w[2 * i + 1] != 0u || w[2 * i] >= (unsigned)TTOT) { ok = 0; break; }
        }
        is64 = ok;
    }
    if (t < TTOT) flags[t] = 1;
    __syncthreads();

    if (is64) {
        const long long* m64 = (const long long*)mids_raw;
        for (int i = t; i < NMASK; i += blockDim.x)
            flags[(int)m64[(size_t)b * NMASK + i]] = 0;
    } else {
        const int* m32 = (const int*)mids_raw;
        for (int i = t; i < NMASK; i += blockDim.x)
            flags[m32[b * NMASK + i]] = 0;
    }
    __syncthreads();

    const int f = (t < TTOT) ? flags[t] : 0;
    scanv[t] = f;
    for (int off = 1; off < 512; off <<= 1) {
        __syncthreads();
        int v = scanv[t];
        int u = (t >= off) ? scanv[t - off] : 0;
        __syncthreads();
        scanv[t] = v + u;
    }
    __syncthreads();

    if (t < TTOT) {
        if (f) {
            int r = scanv[t] - 1;
            g_rank[b * TTOT + t] = r;
            g_vis_tok[b * NVIS + r] = t;
        } else {
            g_rank[b * TTOT + t] = -1;
        }
    }
}

// ---------------------------------------------------------------------------
// Kernel D: convert x and W to fp16 scratch (8 elems / thread).
// ---------------------------------------------------------------------------
#define XCH (MROWS * ENC / 8)    // 1605632 chunks of 8
#define WCH (DEC * ENC / 8)      // 65536
__global__ void convert_fp16_kernel(const float* __restrict__ x,
                                    const float* __restrict__ W) {
    const int i = blockIdx.x * blockDim.x + threadIdx.x;
    const float4* src;
    uint4* dst;
    int c;
    if (i < XCH) {
        src = (const float4*)x; dst = (uint4*)g_xh; c = i;
    } else if (i < XCH + WCH) {
        src = (const float4*)W; dst = (uint4*)g_wh; c = i - XCH;
    } else return;

    float4 v0 = src[2 * c], v1 = src[2 * c + 1];
    __half2 h0 = __float22half2_rn(make_float2(v0.x, v0.y));
    __half2 h1 = __float22half2_rn(make_float2(v0.z, v0.w));
    __half2 h2 = __float22half2_rn(make_float2(v1.x, v1.y));
    __half2 h3 = __float22half2_rn(make_float2(v1.z, v1.w));
    uint4 o;
    o.x = *(uint32_t*)&h0; o.y = *(uint32_t*)&h1;
    o.z = *(uint32_t*)&h2; o.w = *(uint32_t*)&h3;
    dst[c] = o;
}

// ---------------------------------------------------------------------------
// Kernel C: fill masked rows with mask_token + pos_embed + view_embed.
// ---------------------------------------------------------------------------
__global__ void fill_masked_kernel(const float* __restrict__ mask_token,
                                   const float* __restrict__ pos,
                                   const float* __restrict__ ve,
                                   float* __restrict__ out) {
    const int warp = (blockIdx.x * blockDim.x + threadIdx.x) >> 5;
    const int lane = threadIdx.x & 31;
    if (warp >= BATCH * TTOT) return;
    if (g_rank[warp] >= 0) return;

    const int t = warp % TTOT;
    const float4* mt = (const float4*)mask_token;
    const float4* pp = (const float4*)(pos + (size_t)t * DEC);
    const float4* vv = (const float4*)(ve + (size_t)(t >= TVIEW) * DEC);
    float4* o = (float4*)(out + (size_t)warp * DEC);

    #pragma unroll
    for (int j = 0; j < 4; j++) {
        int i = lane + j * 32;
        float4 a = mt[i], p = pp[i], c = vv[i];
        o[i] = make_float4(a.x + p.x + c.x, a.y + p.y + c.y,
                           a.z + p.z + c.z, a.w + p.w + c.w);
    }
}

// ---------------------------------------------------------------------------
// Kernel B: fp16 mma.sync GEMM (M=12544, N=512, K=1024), scatter epilogue.
// CTA 128x128, BK=32, 4-stage cp.async, 16 warps (4x4), warp tile 32x32.
// ---------------------------------------------------------------------------
#define BK 32
#define NSTG 4
#define LDA 40                       // halfs per row (32 + 8 pad -> 80B rows)
#define STAGE_A_BYTES (128 * LDA * 2)    // 10240
#define STAGE_BYTES   (2 * STAGE_A_BYTES)  // A + B = 20480
#define SMEM_TOTAL (NSTG * STAGE_BYTES)    // 81920
#define LDC 132

__global__ void __launch_bounds__(512, 1)
gemm_scatter_mma(const float* __restrict__ bias,
                 const float* __restrict__ pos,
                 const float* __restrict__ ve,
                 float* __restrict__ out) {
    extern __shared__ char smem[];
    const uint32_t sbase = smem_u32(smem);

    const int tid  = threadIdx.x;
    const int wid  = tid >> 5;
    const int lane = tid & 31;
    const int wm = wid & 3;          // warp row (4)
    const int wn = wid >> 2;         // warp col (4)

    const int bn = blockIdx.x;       // 0..3  fast -> x L2 reuse
    const int bm = blockIdx.y;       // 0..97
    const int row0 = bm * 128;
    const int n0 = bn * 128;

    // cp.async mapping: thread t loads A chunk t and B chunk t (16B each)
    const int car = tid >> 2;        // 0..127 row
    const int cac = tid & 3;         // 0..3 chunk
    const __half* srcA0 = g_xh + (size_t)(row0 + car) * ENC + cac * 8;
    const __half* srcB0 = g_wh + (size_t)(n0 + car) * ENC + cac * 8;
    const uint32_t dstOff = car * (LDA * 2) + cac * 16;

    // ldmatrix per-thread offsets (byte, within stage)
    const int arow = wm * 32 + (lane & 15);
    const int acol = (lane >> 4) << 3;
    const int brow = wn * 32 + (lane & 7) + ((lane >> 4) << 3);
    const int bcol = ((lane >> 3) & 1) << 3;

    float acc[2][4][4];
    #pragma unroll
    for (int i = 0; i < 2; i++)
        #pragma unroll
        for (int j = 0; j < 4; j++)
            #pragma unroll
            for (int k = 0; k < 4; k++) acc[i][j][k] = 0.f;

    // prologue: stages 0..2
    #pragma unroll
    for (int s = 0; s < NSTG - 1; s++) {
        const uint32_t sa = sbase + s * STAGE_BYTES;
        cp_async16(sa + dstOff, srcA0 + s * BK);
        cp_async16(sa + STAGE_A_BYTES + dstOff, srcB0 + s * BK);
        CP_COMMIT();
    }

    #pragma unroll 1
    for (int s = 0; s < ENC / BK; s++) {
        CP_WAIT(2);
        __syncthreads();

        if (s + NSTG - 1 < ENC / BK) {
            const int sp = s + NSTG - 1;
            const uint32_t sa = sbase + (sp & (NSTG - 1)) * STAGE_BYTES;
            cp_async16(sa + dstOff, srcA0 + sp * BK);
            cp_async16(sa + STAGE_A_BYTES + dstOff, srcB0 + sp * BK);
        }
        CP_COMMIT();

        const uint32_t sa = sbase + (s & (NSTG - 1)) * STAGE_BYTES;
        const uint32_t sb = sa + STAGE_A_BYTES;

        #pragma unroll
        for (int ks = 0; ks < 2; ks++) {
            uint32_t a[2][4], b[2][4];
            #pragma unroll
            for (int mt = 0; mt < 2; mt++)
                ldsm4(a[mt], sa + ((arow + mt * 16) * LDA + ks * 16 + acol) * 2);
            #pragma unroll
            for (int p = 0; p < 2; p++)
                ldsm4(b[p], sb + ((brow + p * 16) * LDA + ks * 16 + bcol) * 2);
            #pragma unroll
            for (int mt = 0; mt < 2; mt++)
                #pragma unroll
                for (int nt = 0; nt < 4; nt++)
                    mma16816(acc[mt][nt], a[mt], &b[nt >> 1][(nt & 1) * 2]);
        }
    }

    __syncthreads();   // all ldmatrix done before overwriting smem with C

    // stage C to smem
    float* Cs = (float*)smem;
    const int g = lane >> 2, t2 = (lane & 3) * 2;
    #pragma unroll
    for (int mt = 0; mt < 2; mt++) {
        #pragma unroll
        for (int nt = 0; nt < 4; nt++) {
            const int r = wm * 32 + mt * 16 + g;
            const int c = wn * 32 + nt * 8 + t2;
            *(float2*)(Cs + r * LDC + c) = make_float2(acc[mt][nt][0], acc[mt][nt][1]);
            *(float2*)(Cs + (r + 8) * LDC + c) = make_float2(acc[mt][nt][2], acc[mt][nt][3]);
        }
    }
    __syncthreads();

    // scatter rows: warp w -> rows w*8 .. w*8+7, lane covers 128 cols (float4)
    const int col = lane * 4;
    const float4 bb = *(const float4*)(bias + n0 + col);
    #pragma unroll
    for (int i = 0; i < 8; i++) {
        const int r = wid * 8 + i;
        const int mrow = row0 + r;
        const int b = mrow / NVIS;
        const int tok = g_vis_tok[mrow];
        const int viewi = (tok >= TVIEW);
        float4 c = *(float4*)(Cs + r * LDC + col);
        float4 p = *(const float4*)(pos + (size_t)tok * DEC + n0 + col);
        float4 v = *(const float4*)(ve + (size_t)viewi * DEC + n0 + col);
        float4 o;
        o.x = c.x + p.x + v.x + bb.x;
        o.y = c.y + p.y + v.y + bb.y;
        o.z = c.z + p.z + v.z + bb.z;
        o.w = c.w + p.w + v.w + bb.w;
        *(float4*)(out + ((size_t)(b * TTOT + tok)) * DEC + n0 + col) = o;
    }
}

// ---------------------------------------------------------------------------
extern "C" void kernel_launch(void* const* d_in, const int* in_sizes, int n_in,
                              void* d_out, int out_size) {
    const float* x          = (const float*)d_in[0];
    const void*  mids       = d_in[1];
    const float* W          = (const float*)d_in[2];
    const float* bias       = (const float*)d_in[3];
    const float* mask_token = (const float*)d_in[4];
    const float* pos        = (const float*)d_in[5];
    const float* ve         = (const float*)d_in[6];
    float* out = (float*)d_out;

    // fp16 conversion of x and W
    {
        const int total = XCH + WCH;
        convert_fp16_kernel<<<(total + 255) / 256, 256>>>(x, W);
    }

    build_index_kernel<<<BATCH, 512>>>(mids);

    {
        const int nwarps = BATCH * TTOT;
        const int threads = 256;
        const int blocks = (nwarps * 32 + threads - 1) / threads;
        fill_masked_kernel<<<blocks, threads>>>(mask_token, pos, ve, out);
    }

    {
        cudaFuncSetAttribute(gemm_scatter_mma,
                             cudaFuncAttributeMaxDynamicSharedMemorySize, SMEM_TOTAL);
        dim3 grid(4, 98);
        gemm_scatter_mma<<<grid, 512, SMEM_TOTAL>>>(bias, pos, ve, out);
    }
}